// round 1
// baseline (speedup 1.0000x reference)
#include <cuda_runtime.h>
#include <stdint.h>

#define B 8192
#define D 512
#define ROWS_PER_BLOCK 4
#define AM_THREADS 256

__device__ int   g_idx_p[B];
__device__ int   g_idx_n[B];
__device__ float g_rowloss[B];

__device__ __forceinline__ void threefry2x32(uint32_t k0, uint32_t k1,
                                             uint32_t x0, uint32_t x1,
                                             uint32_t& y0, uint32_t& y1) {
    uint32_t ks2 = k0 ^ k1 ^ 0x1BD11BDAu;
    x0 += k0; x1 += k1;
#define TF_RND(r) { x0 += x1; x1 = __funnelshift_l(x1, x1, (r)); x1 ^= x0; }
    TF_RND(13) TF_RND(15) TF_RND(26) TF_RND(6)
    x0 += k1;  x1 += ks2 + 1u;
    TF_RND(17) TF_RND(29) TF_RND(16) TF_RND(24)
    x0 += ks2; x1 += k0 + 2u;
    TF_RND(13) TF_RND(15) TF_RND(26) TF_RND(6)
    x0 += k0;  x1 += k1 + 3u;
    TF_RND(17) TF_RND(29) TF_RND(16) TF_RND(24)
    x0 += k1;  x1 += ks2 + 4u;
    TF_RND(13) TF_RND(15) TF_RND(26) TF_RND(6)
    x0 += ks2; x1 += k0 + 5u;
#undef TF_RND
    y0 = x0; y1 = x1;
}

// One block handles ROWS_PER_BLOCK consecutive rows. For each row r and every
// column c, compute the partitionable-threefry random bits for either the
// positive-gumbel matrix (key kp, if labels match) or the negative matrix
// (key kn). Argmax over bits>>9 (monotone in gumbel value) with first-index
// tie-break, done by packing (bits23 << 13) | (8191 - c) and taking max.
__global__ void __launch_bounds__(AM_THREADS) argmax_kernel(const int* __restrict__ labels) {
    __shared__ int slab[B];                 // 32 KB
    __shared__ unsigned long long sredp[AM_THREADS / 32];
    __shared__ unsigned long long sredn[AM_THREADS / 32];

    const int tid = threadIdx.x;
    for (int i = tid; i < B; i += AM_THREADS) slab[i] = labels[i];
    __syncthreads();

    // Derive kp, kn exactly as jax.random.split(jax.random.key(42)) with
    // threefry_partitionable=True (fold-like split over 64-bit iota {0,1}).
    uint32_t kp0, kp1, kn0, kn1;
    threefry2x32(0u, 42u, 0u, 0u, kp0, kp1);
    threefry2x32(0u, 42u, 0u, 1u, kn0, kn1);

    const int r0 = blockIdx.x * ROWS_PER_BLOCK;

    for (int rr = 0; rr < ROWS_PER_BLOCK; rr++) {
        const int r = r0 + rr;
        const int myl = slab[r];
        const uint32_t base = (uint32_t)r << 13;   // r * B, fits in 26 bits

        unsigned long long bp = 0ull, bn = 0ull;

        for (int c = tid; c < B; c += AM_THREADS) {
            const bool pos = (slab[c] == myl);
            const uint32_t k0 = pos ? kp0 : kn0;
            const uint32_t k1 = pos ? kp1 : kn1;
            uint32_t y0, y1;
            threefry2x32(k0, k1, 0u, base + (uint32_t)c, y0, y1);
            const uint32_t bits23 = (y0 ^ y1) >> 9;
            const unsigned long long packed =
                ((unsigned long long)bits23 << 13) | (unsigned long long)(8191 - c);
            if (pos) { if (packed > bp) bp = packed; }
            else     { if (packed > bn) bn = packed; }
        }

        // warp max
        for (int off = 16; off > 0; off >>= 1) {
            unsigned long long o;
            o = __shfl_down_sync(0xFFFFFFFFu, bp, off); if (o > bp) bp = o;
            o = __shfl_down_sync(0xFFFFFFFFu, bn, off); if (o > bn) bn = o;
        }
        const int w = tid >> 5;
        if ((tid & 31) == 0) { sredp[w] = bp; sredn[w] = bn; }
        __syncthreads();
        if (tid == 0) {
            unsigned long long mp = sredp[0], mn = sredn[0];
            #pragma unroll
            for (int i = 1; i < AM_THREADS / 32; i++) {
                if (sredp[i] > mp) mp = sredp[i];
                if (sredn[i] > mn) mn = sredn[i];
            }
            g_idx_p[r] = 8191 - (int)(mp & 0x1FFFull);
            g_idx_n[r] = 8191 - (int)(mn & 0x1FFFull);
        }
        __syncthreads();
    }
}

// Per-row hinge: cos(a, p) - cos(a, n) + margin, clamped at 0.
// Norms are fused (5 dot products of length 512 per row).
__global__ void __launch_bounds__(128) loss_kernel(const float* __restrict__ pred) {
    __shared__ float sred[5][4];
    const int r = blockIdx.x;
    const int tid = threadIdx.x;
    const int ip = g_idx_p[r];
    const int in_ = g_idx_n[r];
    const float* __restrict__ a = pred + (size_t)r   * D;
    const float* __restrict__ p = pred + (size_t)ip  * D;
    const float* __restrict__ n = pred + (size_t)in_ * D;

    float saa = 0.f, spp = 0.f, snn = 0.f, sap = 0.f, san = 0.f;
    for (int j = tid; j < D; j += 128) {
        const float av = a[j], pv = p[j], nv = n[j];
        saa += av * av; spp += pv * pv; snn += nv * nv;
        sap += av * pv; san += av * nv;
    }
    for (int off = 16; off > 0; off >>= 1) {
        saa += __shfl_down_sync(0xFFFFFFFFu, saa, off);
        spp += __shfl_down_sync(0xFFFFFFFFu, spp, off);
        snn += __shfl_down_sync(0xFFFFFFFFu, snn, off);
        sap += __shfl_down_sync(0xFFFFFFFFu, sap, off);
        san += __shfl_down_sync(0xFFFFFFFFu, san, off);
    }
    const int w = tid >> 5;
    if ((tid & 31) == 0) {
        sred[0][w] = saa; sred[1][w] = spp; sred[2][w] = snn;
        sred[3][w] = sap; sred[4][w] = san;
    }
    __syncthreads();
    if (tid == 0) {
        float t0 = 0, t1 = 0, t2 = 0, t3 = 0, t4 = 0;
        #pragma unroll
        for (int i = 0; i < 4; i++) {
            t0 += sred[0][i]; t1 += sred[1][i]; t2 += sred[2][i];
            t3 += sred[3][i]; t4 += sred[4][i];
        }
        const float na = fmaxf(sqrtf(t0), 1e-6f);
        const float np = fmaxf(sqrtf(t1), 1e-6f);
        const float nn = fmaxf(sqrtf(t2), 1e-6f);
        const float cosp = t3 / (na * np);
        const float cosn = t4 / (na * nn);
        g_rowloss[r] = fmaxf(cosp - cosn + 0.1f, 0.0f);
    }
}

__global__ void __launch_bounds__(1024) reduce_kernel(float* __restrict__ out) {
    __shared__ float s[1024];
    const int tid = threadIdx.x;
    float v = 0.f;
    for (int i = tid; i < B; i += 1024) v += g_rowloss[i];
    s[tid] = v;
    __syncthreads();
    for (int st = 512; st > 0; st >>= 1) {
        if (tid < st) s[tid] += s[tid + st];
        __syncthreads();
    }
    if (tid == 0) out[0] = s[0] * (1.0f / (float)B);
}

extern "C" void kernel_launch(void* const* d_in, const int* in_sizes, int n_in,
                              void* d_out, int out_size) {
    const float* pred   = (const float*)d_in[0];
    const int*   labels = (const int*)d_in[1];
    float* out = (float*)d_out;

    argmax_kernel<<<B / ROWS_PER_BLOCK, AM_THREADS>>>(labels);
    loss_kernel<<<B, 128>>>(pred);
    reduce_kernel<<<1, 1024>>>(out);
}